// round 2
// baseline (speedup 1.0000x reference)
#include <cuda_runtime.h>
#include <cstdint>
#include <math.h>

#define B_SZ 16384
#define H_SZ 512
#define G4   2048      // 4*H
#define OUTF 256
#define KPAD 288       // 257 padded up to multiple of 32
#define IN0  257

// ---------------- scratch (static device memory; no allocation at runtime) ----
__device__ float g_inpPad[(size_t)B_SZ * KPAD];      // [B,288] zero-padded concat(x,y)
__device__ float g_WxPad [(size_t)G4 * KPAD];        // [2048,288] zero-padded Wx0
__device__ float g_Zx    [(size_t)B_SZ * G4];        // pre-BN gates (input path)
__device__ float g_Zh    [(size_t)B_SZ * G4];        // pre-BN gates (hidden path)
__device__ float g_part  [2 * 8 * G4 * 2];           // partial sums: [x/h][rowchunk][col][sum,sq]
__device__ float g_scaleX[G4], g_shiftX[G4], g_scaleH[G4], g_shiftH[G4];

// ---------------- helpers ----------------------------------------------------
__device__ __forceinline__ uint32_t f2tf(float f) {
    // round-to-nearest-even f32 -> tf32 (19-bit mantissa container)
    uint32_t u = __float_as_uint(f);
    uint32_t r = u + 0xFFFu + ((u >> 13) & 1u);
    return r & 0xFFFFE000u;
}
__device__ __forceinline__ float sigm(float x) { return 1.f / (1.f + expf(-x)); }

// ---------------- prep kernels -----------------------------------------------
__global__ void prep_inp(const float* __restrict__ x, const float* __restrict__ y,
                         float* __restrict__ o) {
    int idx = blockIdx.x * blockDim.x + threadIdx.x;   // B*KPAD threads
    int b = idx / KPAD, k = idx - b * KPAD;
    float v = (k < 256) ? x[(size_t)b * 256 + k] : (k == 256 ? y[b] : 0.f);
    o[idx] = v;
}
__global__ void prep_wx(const float* __restrict__ Wx, float* __restrict__ o) {
    int idx = blockIdx.x * blockDim.x + threadIdx.x;   // G4*KPAD threads
    int r = idx / KPAD, k = idx - r * KPAD;
    o[idx] = (k < IN0) ? Wx[(size_t)r * IN0 + k] : 0.f;
}

// ---------------- tf32 tensor-core GEMM: C[M,N] = A[M,K] * W[N,K]^T (+bias) ---
// block tile 128x128, BK=32, 8 warps (4x2), warp tile 32x64, mma m16n8k8 tf32
constexpr int BM = 128, BN = 128, BK = 32, PADX = 4;

__global__ __launch_bounds__(256, 2) void gemm_tn(
    float* __restrict__ C, const float* __restrict__ A, int lda,
    const float* __restrict__ W, int ldw, int M, int N, int K,
    const float* __restrict__ bias)
{
    __shared__ uint32_t As[BM][BK + PADX];
    __shared__ uint32_t Ws[BN][BK + PADX];
    const int tid  = threadIdx.x;
    const int lane = tid & 31, warp = tid >> 5;
    const int g    = lane >> 2, tg = lane & 3;       // groupID, threadID_in_group
    const int wm   = warp >> 1, wn = warp & 1;
    const int mW   = wm * 32, nW = wn * 64;
    const int bM   = blockIdx.y * BM, bN = blockIdx.x * BN;

    float acc[2][8][4];
#pragma unroll
    for (int i = 0; i < 2; i++)
#pragma unroll
        for (int j = 0; j < 8; j++)
#pragma unroll
            for (int r = 0; r < 4; r++) acc[i][j][r] = 0.f;

    for (int k0 = 0; k0 < K; k0 += BK) {
        float4 av[4], wv[4];
#pragma unroll
        for (int i = 0; i < 4; i++) {
            int idx = tid + i * 256;
            int r = idx >> 3, c4 = idx & 7;          // 8 float4 per 32-float row
            av[i] = *(const float4*)(A + (size_t)(bM + r) * lda + (k0 + c4 * 4));
            wv[i] = *(const float4*)(W + (size_t)(bN + r) * ldw + (k0 + c4 * 4));
        }
        __syncthreads();   // previous iteration's compute done before overwrite
#pragma unroll
        for (int i = 0; i < 4; i++) {
            int idx = tid + i * 256;
            int r = idx >> 3, c = (idx & 7) * 4;
            As[r][c + 0] = f2tf(av[i].x); As[r][c + 1] = f2tf(av[i].y);
            As[r][c + 2] = f2tf(av[i].z); As[r][c + 3] = f2tf(av[i].w);
            Ws[r][c + 0] = f2tf(wv[i].x); Ws[r][c + 1] = f2tf(wv[i].y);
            Ws[r][c + 2] = f2tf(wv[i].z); Ws[r][c + 3] = f2tf(wv[i].w);
        }
        __syncthreads();
#pragma unroll
        for (int kk = 0; kk < BK; kk += 8) {
            uint32_t a[2][4], b[8][2];
#pragma unroll
            for (int mt = 0; mt < 2; mt++) {
                int r0 = mW + mt * 16 + g;
                a[mt][0] = As[r0    ][kk + tg];
                a[mt][1] = As[r0 + 8][kk + tg];
                a[mt][2] = As[r0    ][kk + tg + 4];
                a[mt][3] = As[r0 + 8][kk + tg + 4];
            }
#pragma unroll
            for (int nt = 0; nt < 8; nt++) {
                int rn = nW + nt * 8 + g;
                b[nt][0] = Ws[rn][kk + tg];
                b[nt][1] = Ws[rn][kk + tg + 4];
            }
#pragma unroll
            for (int mt = 0; mt < 2; mt++)
#pragma unroll
                for (int nt = 0; nt < 8; nt++)
                    asm volatile(
                        "mma.sync.aligned.m16n8k8.row.col.f32.tf32.tf32.f32 "
                        "{%0,%1,%2,%3},{%4,%5,%6,%7},{%8,%9},{%0,%1,%2,%3};\n"
                        : "+f"(acc[mt][nt][0]), "+f"(acc[mt][nt][1]),
                          "+f"(acc[mt][nt][2]), "+f"(acc[mt][nt][3])
                        : "r"(a[mt][0]), "r"(a[mt][1]), "r"(a[mt][2]), "r"(a[mt][3]),
                          "r"(b[nt][0]), "r"(b[nt][1]));
        }
    }
    // epilogue
#pragma unroll
    for (int mt = 0; mt < 2; mt++) {
        int r0 = bM + mW + mt * 16 + g;
#pragma unroll
        for (int nt = 0; nt < 8; nt++) {
            int c = bN + nW + nt * 8 + 2 * tg;
            float b0 = bias ? bias[c] : 0.f;
            float b1 = bias ? bias[c + 1] : 0.f;
            float2 v0 = make_float2(acc[mt][nt][0] + b0, acc[mt][nt][1] + b1);
            float2 v1 = make_float2(acc[mt][nt][2] + b0, acc[mt][nt][3] + b1);
            *(float2*)(C + (size_t)r0 * N + c)       = v0;
            *(float2*)(C + (size_t)(r0 + 8) * N + c) = v1;
        }
    }
}

// ---------------- BN statistics (deterministic two-stage) ---------------------
// stage 1: grid (64 colblocks, 8 rowchunks), 256 thr = 32 cols x 8 rowlanes
__global__ void stats_partial(const float* __restrict__ Z, float* __restrict__ part) {
    const int col = threadIdx.x & 31;
    const int rl  = threadIdx.x >> 5;
    const int cg  = blockIdx.x * 32 + col;
    const int rB  = blockIdx.y * 2048;
    float s = 0.f, q = 0.f;
    for (int r = rB + rl; r < rB + 2048; r += 8) {
        float v = Z[(size_t)r * G4 + cg];
        s += v; q += v * v;
    }
    __shared__ float ss[8][32], qq[8][32];
    ss[rl][col] = s; qq[rl][col] = q;
    __syncthreads();
    for (int st = 4; st > 0; st >>= 1) {
        if (rl < st) { ss[rl][col] += ss[rl + st][col]; qq[rl][col] += qq[rl + st][col]; }
        __syncthreads();
    }
    if (rl == 0) {
        size_t o = ((size_t)blockIdx.y * G4 + cg) * 2;
        part[o] = ss[0][col]; part[o + 1] = qq[0][col];
    }
}

// stage 2: fold stats into affine scale/shift for both BN branches
__global__ void stats_final(const float* __restrict__ pX, const float* __restrict__ gx,
                            const float* __restrict__ bx, float* __restrict__ scX,
                            float* __restrict__ shX,
                            const float* __restrict__ pH, const float* __restrict__ gh,
                            const float* __restrict__ bh, float* __restrict__ scH,
                            float* __restrict__ shH) {
    int j = blockIdx.x * blockDim.x + threadIdx.x;   // 2048 threads
    float sx = 0.f, qx = 0.f, sh = 0.f, qh = 0.f;
#pragma unroll
    for (int y = 0; y < 8; y++) {
        size_t o = ((size_t)y * G4 + j) * 2;
        sx += pX[o]; qx += pX[o + 1];
        sh += pH[o]; qh += pH[o + 1];
    }
    const float invB = 1.f / (float)B_SZ;
    float mx = sx * invB, vx = qx * invB - mx * mx;
    float ax = gx[j] * rsqrtf(vx + 1e-5f);
    scX[j] = ax; shX[j] = bx[j] - mx * ax;
    float mh = sh * invB, vh = qh * invB - mh * mh;
    float ah = gh[j] * rsqrtf(vh + 1e-5f);
    scH[j] = ah; shH[j] = bh[j] - mh * ah;
}

// ---------------- fused BN + LSTM cell elementwise ----------------------------
__global__ void cell_kernel(const float* __restrict__ Zx, const float* __restrict__ Zh,
                            const float* __restrict__ scX, const float* __restrict__ shX,
                            const float* __restrict__ scH, const float* __restrict__ shH,
                            const float* __restrict__ cPrev,
                            float* __restrict__ hOut, float* __restrict__ cOut) {
    int idx = blockIdx.x * blockDim.x + threadIdx.x;  // B*512 threads
    int j = idx & 511;
    size_t base = ((size_t)(idx >> 9)) * G4 + j;
    float zf = Zx[base       ] * scX[j       ] + shX[j       ] + Zh[base       ] * scH[j       ] + shH[j       ];
    float zi = Zx[base +  512] * scX[j +  512] + shX[j +  512] + Zh[base +  512] * scH[j +  512] + shH[j +  512];
    float zo = Zx[base + 1024] * scX[j + 1024] + shX[j + 1024] + Zh[base + 1024] * scH[j + 1024] + shH[j + 1024];
    float zg = Zx[base + 1536] * scX[j + 1536] + shX[j + 1536] + Zh[base + 1536] * scH[j + 1536] + shH[j + 1536];
    float c2 = sigm(zf) * cPrev[idx] + sigm(zi) * tanhf(zg);
    hOut[idx] = sigm(zo) * tanhf(c2);
    cOut[idx] = c2;
}

// ---------------- launch ------------------------------------------------------
extern "C" void kernel_launch(void* const* d_in, const int* in_sizes, int n_in,
                              void* d_out, int out_size) {
    const float* x   = (const float*)d_in[0];
    const float* y   = (const float*)d_in[1];
    const float* h0  = (const float*)d_in[2];
    const float* c0  = (const float*)d_in[3];
    const float* Wx0 = (const float*)d_in[4];
    const float* Wh0 = (const float*)d_in[5];
    const float* gx0 = (const float*)d_in[6];
    const float* bx0 = (const float*)d_in[7];
    const float* gh0 = (const float*)d_in[8];
    const float* bh0 = (const float*)d_in[9];
    const float* Wx1 = (const float*)d_in[10];
    const float* Wh1 = (const float*)d_in[11];
    const float* gx1 = (const float*)d_in[12];
    const float* bx1 = (const float*)d_in[13];
    const float* gh1 = (const float*)d_in[14];
    const float* bh1 = (const float*)d_in[15];
    const float* Wo  = (const float*)d_in[16];
    const float* bo  = (const float*)d_in[17];
    float* out = (float*)d_out;

    float *inp, *wxp, *Zx, *Zh, *part, *scX, *shX, *scH, *shH;
    cudaGetSymbolAddress((void**)&inp,  g_inpPad);
    cudaGetSymbolAddress((void**)&wxp,  g_WxPad);
    cudaGetSymbolAddress((void**)&Zx,   g_Zx);
    cudaGetSymbolAddress((void**)&Zh,   g_Zh);
    cudaGetSymbolAddress((void**)&part, g_part);
    cudaGetSymbolAddress((void**)&scX,  g_scaleX);
    cudaGetSymbolAddress((void**)&shX,  g_shiftX);
    cudaGetSymbolAddress((void**)&scH,  g_scaleH);
    cudaGetSymbolAddress((void**)&shH,  g_shiftH);

    // output layout: out[B,256], h1[B,512], h2[B,512], c1[B,512], c2[B,512]
    float* h1 = out + (size_t)B_SZ * OUTF;
    float* h2 = h1 + (size_t)B_SZ * H_SZ;
    float* c1 = h2 + (size_t)B_SZ * H_SZ;
    float* c2 = c1 + (size_t)B_SZ * H_SZ;
    const float* h00 = h0;
    const float* h01 = h0 + (size_t)B_SZ * H_SZ;
    const float* c00 = c0;
    const float* c01 = c0 + (size_t)B_SZ * H_SZ;

    float* partX = part;
    float* partH = part + 8 * G4 * 2;

    dim3 gg(G4 / BN, B_SZ / BM);
    dim3 go(OUTF / BN, B_SZ / BM);
    dim3 gs(G4 / 32, 8);

    prep_inp<<<(B_SZ * KPAD) / 256, 256>>>(x, y, inp);
    prep_wx<<<(G4 * KPAD) / 256, 256>>>(Wx0, wxp);

    // layer 0
    gemm_tn<<<gg, 256>>>(Zx, inp, KPAD, wxp, KPAD, B_SZ, G4, KPAD, nullptr);
    gemm_tn<<<gg, 256>>>(Zh, h00, H_SZ, Wh0, H_SZ, B_SZ, G4, H_SZ, nullptr);
    stats_partial<<<gs, 256>>>(Zx, partX);
    stats_partial<<<gs, 256>>>(Zh, partH);
    stats_final<<<8, 256>>>(partX, gx0, bx0, scX, shX, partH, gh0, bh0, scH, shH);
    cell_kernel<<<(B_SZ * H_SZ) / 256, 256>>>(Zx, Zh, scX, shX, scH, shH, c00, h1, c1);

    // layer 1
    gemm_tn<<<gg, 256>>>(Zx, h1, H_SZ, Wx1, H_SZ, B_SZ, G4, H_SZ, nullptr);
    gemm_tn<<<gg, 256>>>(Zh, h01, H_SZ, Wh1, H_SZ, B_SZ, G4, H_SZ, nullptr);
    stats_partial<<<gs, 256>>>(Zx, partX);
    stats_partial<<<gs, 256>>>(Zh, partH);
    stats_final<<<8, 256>>>(partX, gx1, bx1, scX, shX, partH, gh1, bh1, scH, shH);
    cell_kernel<<<(B_SZ * H_SZ) / 256, 256>>>(Zx, Zh, scX, shX, scH, shH, c01, h2, c2);

    // output projection
    gemm_tn<<<go, 256>>>(out, h2, H_SZ, Wo, H_SZ, B_SZ, OUTF, H_SZ, bo);
}